// round 14
// baseline (speedup 1.0000x reference)
#include <cuda_runtime.h>
#include <cstdint>

// Problem constants (fixed by the reference)
#define BATCH 4
#define CHAN  256
#define HH    192
#define WW    192
#define HW    (HH*WW)
#define MAXD  4
#define WIN   9
#define NDISP 81

// Tiling
#define TILE_X 32
#define TILE_Y 4
#define PX     4                 // pixels per thread along x
#define NTX    (TILE_X / PX)     // 8
#define SROWS  (TILE_Y + 2*MAXD) // 12
#define SVEC   10                // float4s per S row (40 cols)
#define SPITCH 44                // 176B row: conflict-free, 16B aligned
#define FPITCH 36                // 144B row: conflict-free, 16B aligned
#define CH     8
#define NROUNDS (CHAN / CH)      // 32
#define NTHREADS (NTX * TILE_Y * WIN)  // 288 = 9 warps, one dy per warp

#define S_VECS (CH * SROWS * SVEC)        // 960 float4 per stage
#define F_VECS (CH * TILE_Y * (TILE_X/4)) // 256 float4 per stage
#define S_ROLES 4                          // 3 full * 288 + 96

#define S_BUF_BYTES (CH * SROWS * SPITCH * 4)   // 16896
#define F_BUF_BYTES (CH * TILE_Y * FPITCH * 4)  // 4608

typedef unsigned long long u64;

__device__ __forceinline__ void cp_async16(uint32_t saddr, const float* gptr, uint32_t full)
{
    int sz = full ? 16 : 0;   // src-size 0 -> 16B zero fill (halo)
    asm volatile("cp.async.cg.shared.global [%0], [%1], 16, %2;\n"
                 :: "r"(saddr), "l"(gptr), "r"(sz));
}

// pack two floats into b64; adjacent float4 members coalesce to 0 MOVs
__device__ __forceinline__ u64 pk(float lo, float hi)
{
    u64 v;
    asm("mov.b64 %0, {%1, %2};" : "=l"(v) : "f"(lo), "f"(hi));
    return v;
}

__device__ __forceinline__ void ffma2(u64& acc, u64 a, u64 b)
{
    asm("fma.rn.f32x2 %0, %1, %2, %3;" : "=l"(acc) : "l"(a), "l"(b), "l"(acc));
}

__device__ __forceinline__ void unpk(u64 v, float& lo, float& hi)
{
    asm("mov.b64 {%0, %1}, %2;" : "=f"(lo), "=f"(hi) : "l"(v));
}

__global__ __launch_bounds__(NTHREADS, 3)
void corr_kernel(const float* __restrict__ F,
                 const float* __restrict__ S,
                 float* __restrict__ out)
{
    __shared__ __align__(16) float sS[2][CH][SROWS][SPITCH];
    __shared__ __align__(16) float sF[2][CH][TILE_Y][FPITCH];

    const int tx = threadIdx.x;            // 0..7
    const int ty = threadIdx.y;            // 0..3
    const int g  = threadIdx.z;            // 0..8 (dy) == warp id
    const int tid = tx + NTX * ty + NTX * TILE_Y * g;

    const int tileX = blockIdx.x * TILE_X;
    const int tileY = blockIdx.y * TILE_Y;
    const int b     = blockIdx.z;

    const float* Fb = F + (size_t)b * CHAN * HW;
    const float* Sb = S + (size_t)b * CHAN * HW;

    // ---------------- precompute load roles (compact 32-bit state) ----------------
    uint32_t s_off[S_ROLES];
    uint32_t s_smem[S_ROLES];
    uint32_t pmask = 0;
#pragma unroll
    for (int k = 0; k < S_ROLES; k++) {
        int v   = tid + k * NTHREADS;
        if (v >= S_VECS) v = 0;
        int ch  = v / (SROWS * SVEC);
        int rem = v - ch * (SROWS * SVEC);
        int row = rem / SVEC;
        int c4  = rem - row * SVEC;
        int gy  = tileY + row - MAXD;
        int gx  = tileX + c4 * 4 - MAXD;
        bool inb = (gy >= 0) && (gy < HH) && (gx >= 0) && (gx + 4 <= WW);
        pmask |= (inb ? 1u : 0u) << k;
        s_off[k]  = inb ? (uint32_t)(((size_t)ch * HW + gy * WW + gx) * 4) : 0u;
        s_smem[k] = (uint32_t)__cvta_generic_to_shared(&sS[0][ch][row][c4 * 4]);
    }
    uint32_t f_off;
    uint32_t f_smem;
    {
        int v   = (tid < F_VECS) ? tid : 0;
        int ch  = v >> 5;
        int rem = v & 31;
        int row = rem >> 3;
        int c4  = rem & 7;
        f_off  = (uint32_t)(((size_t)ch * HW + (tileY + row) * WW + tileX + c4 * 4) * 4);
        f_smem = (uint32_t)__cvta_generic_to_shared(&sF[0][ch][row][c4 * 4]);
    }

    // accumulators:
    //  even d = 2j (j=0..4): packed f32x2, Ae[q][j] = pixels (2q, 2q+1)
    //  odd  d = 2j+1 (j=0..3): scalar, Ao[p][j] = pixel p
    u64   Ae[2][5];
    float Ao[4][4];
#pragma unroll
    for (int j = 0; j < 5; j++) { Ae[0][j] = 0ull; Ae[1][j] = 0ull; }
#pragma unroll
    for (int p = 0; p < 4; p++)
#pragma unroll
        for (int j = 0; j < 4; j++) Ao[p][j] = 0.0f;

    const int x0 = PX * tx;      // 0,4,...,28
    const int sy = ty + g;       // 0..11

    // prologue: round 0's loads, all at once
    {
        const char* sB = (const char*)Sb;
        const char* fB = (const char*)Fb;
#pragma unroll
        for (int k = 0; k < S_ROLES; k++) {
            if (k < S_ROLES - 1 || tid < (S_VECS - (S_ROLES - 1) * NTHREADS)) {
                cp_async16(s_smem[k], (const float*)(sB + s_off[k]), (pmask >> k) & 1u);
            }
        }
        if (tid < F_VECS) cp_async16(f_smem, (const float*)(fB + f_off), 1u);
        asm volatile("cp.async.commit_group;\n" ::: "memory");
    }

    for (int r = 0; r < NROUNDS; r++) {
        asm volatile("cp.async.wait_group 0;\n" ::: "memory");
        __syncthreads();

        const int bb = r & 1;
        const uint32_t nbS = (bb ^ 1) ? (uint32_t)S_BUF_BYTES : 0u;
        const uint32_t nbF = (bb ^ 1) ? (uint32_t)F_BUF_BYTES : 0u;
        const bool more = (r + 1 < NROUNDS);
        const uint32_t cOff = (uint32_t)(r + 1) * (CH * HW * 4);
        const char* sB = (const char*)Sb + cOff;
        const char* fB = (const char*)Fb + cOff;

#pragma unroll
        for (int ch = 0; ch < CH; ch++) {
            // ---- spread next-round cp.async issues across channels 0..4 ----
            if (ch < S_ROLES) {            // ch = 0..3 -> S role ch
                if (more && (ch < S_ROLES - 1 || tid < (S_VECS - (S_ROLES - 1) * NTHREADS))) {
                    cp_async16(s_smem[ch] + nbS, (const float*)(sB + s_off[ch]),
                               (pmask >> ch) & 1u);
                }
            }
            if (ch == S_ROLES) {           // ch = 4 -> F copy + commit
                if (more && tid < F_VECS) {
                    cp_async16(f_smem + nbF, (const float*)(fB + f_off), 1u);
                }
                asm volatile("cp.async.commit_group;\n" ::: "memory");
            }

            // ---- compute channel ch ----
            float4 f4 = *(const float4*)&sF[bb][ch][ty][x0];
            const float4* wr4 = (const float4*)&sS[bb][ch][sy][x0];
            float4 w0 = wr4[0];
            float4 w1 = wr4[1];
            float4 w2 = wr4[2];
            float wa[12] = { w0.x, w0.y, w0.z, w0.w,
                             w1.x, w1.y, w1.z, w1.w,
                             w2.x, w2.y, w2.z, w2.w };

            // odd d first: depends only on f4/wa, ready immediately after loads
#pragma unroll
            for (int j = 0; j < 4; j++) {
                Ao[0][j] = fmaf(f4.x, wa[2 * j + 1], Ao[0][j]);
                Ao[1][j] = fmaf(f4.y, wa[2 * j + 2], Ao[1][j]);
                Ao[2][j] = fmaf(f4.z, wa[2 * j + 3], Ao[2][j]);
                Ao[3][j] = fmaf(f4.w, wa[2 * j + 4], Ao[3][j]);
            }

            // even d: packed f32x2 (adjacent-member packs -> 0 MOVs)
            u64 fp0 = pk(f4.x, f4.y);
            u64 fp1 = pk(f4.z, f4.w);
            u64 we[6] = { pk(w0.x, w0.y), pk(w0.z, w0.w),
                          pk(w1.x, w1.y), pk(w1.z, w1.w),
                          pk(w2.x, w2.y), pk(w2.z, w2.w) };
#pragma unroll
            for (int j = 0; j < 5; j++) {
                ffma2(Ae[0][j], fp0, we[j]);
                ffma2(Ae[1][j], fp1, we[j + 1]);
            }
        }
    }

    // ---------------- store: scale by 1/C ----------------
    const float inv = 1.0f / (float)CHAN;
    const int y  = tileY + ty;
    const int gx = tileX + x0;
    // even disparities
#pragma unroll
    for (int j = 0; j < 5; j++) {
        int disp = g * WIN + 2 * j;
        float p0, p1, p2, p3;
        unpk(Ae[0][j], p0, p1);
        unpk(Ae[1][j], p2, p3);
        float4 v = { p0 * inv, p1 * inv, p2 * inv, p3 * inv };
        *(float4*)&out[((size_t)(b * NDISP + disp) * HH + y) * WW + gx] = v;
    }
    // odd disparities
#pragma unroll
    for (int j = 0; j < 4; j++) {
        int disp = g * WIN + 2 * j + 1;
        float4 v = { Ao[0][j] * inv, Ao[1][j] * inv,
                     Ao[2][j] * inv, Ao[3][j] * inv };
        *(float4*)&out[((size_t)(b * NDISP + disp) * HH + y) * WW + gx] = v;
    }
}

extern "C" void kernel_launch(void* const* d_in, const int* in_sizes, int n_in,
                              void* d_out, int out_size)
{
    const float* tensorFirst  = (const float*)d_in[0];
    const float* tensorSecond = (const float*)d_in[1];
    float* out = (float*)d_out;

    dim3 grid(WW / TILE_X, HH / TILE_Y, BATCH);   // 6 x 48 x 4 = 1152
    dim3 block(NTX, TILE_Y, WIN);                 // 8 x 4 x 9 = 288
    corr_kernel<<<grid, block>>>(tensorFirst, tensorSecond, out);
}

// round 15
// speedup vs baseline: 1.0127x; 1.0127x over previous
#include <cuda_runtime.h>
#include <cstdint>

// Problem constants (fixed by the reference)
#define BATCH 4
#define CHAN  256
#define HH    192
#define WW    192
#define HW    (HH*WW)
#define MAXD  4
#define WIN   9
#define NDISP 81

// Tiling
#define TILE_X 32
#define TILE_Y 4
#define PX     4                 // pixels per thread along x
#define NTX    (TILE_X / PX)     // 8
#define SROWS  (TILE_Y + 2*MAXD) // 12
#define SVEC   10                // float4s per S row (40 cols)
#define SPITCH 44                // 176B row: conflict-free, 16B aligned
#define FPITCH 36                // 144B row: conflict-free, 16B aligned
#define CH     8
#define NROUNDS (CHAN / CH)      // 32
#define NTHREADS (NTX * TILE_Y * WIN)  // 288 = 9 warps, one dy per warp

#define S_VECS (CH * SROWS * SVEC)        // 960 float4 per stage
#define F_VECS (CH * TILE_Y * (TILE_X/4)) // 256 float4 per stage
#define S_ROLES 4                          // 3 full * 288 + 96

#define S_BUF_BYTES (CH * SROWS * SPITCH * 4)   // 16896
#define F_BUF_BYTES (CH * TILE_Y * FPITCH * 4)  // 4608

typedef unsigned long long u64;

__device__ __forceinline__ void cp_async16(uint32_t saddr, const float* gptr, uint32_t full)
{
    int sz = full ? 16 : 0;   // src-size 0 -> 16B zero fill (halo)
    asm volatile("cp.async.cg.shared.global [%0], [%1], 16, %2;\n"
                 :: "r"(saddr), "l"(gptr), "r"(sz));
}

// pack two floats into b64; adjacent float4 members coalesce to 0 MOVs
__device__ __forceinline__ u64 pk(float lo, float hi)
{
    u64 v;
    asm("mov.b64 %0, {%1, %2};" : "=l"(v) : "f"(lo), "f"(hi));
    return v;
}

__device__ __forceinline__ void ffma2(u64& acc, u64 a, u64 b)
{
    asm("fma.rn.f32x2 %0, %1, %2, %3;" : "=l"(acc) : "l"(a), "l"(b), "l"(acc));
}

__device__ __forceinline__ void unpk(u64 v, float& lo, float& hi)
{
    asm("mov.b64 {%0, %1}, %2;" : "=f"(lo), "=f"(hi) : "l"(v));
}

__global__ __launch_bounds__(NTHREADS, 3)
void corr_kernel(const float* __restrict__ F,
                 const float* __restrict__ S,
                 float* __restrict__ out)
{
    __shared__ __align__(16) float sS[2][CH][SROWS][SPITCH];
    __shared__ __align__(16) float sF[2][CH][TILE_Y][FPITCH];

    const int tx = threadIdx.x;            // 0..7
    const int ty = threadIdx.y;            // 0..3
    const int g  = threadIdx.z;            // 0..8 (dy) == warp id
    const int tid = tx + NTX * ty + NTX * TILE_Y * g;

    const int tileX = blockIdx.x * TILE_X;
    const int tileY = blockIdx.y * TILE_Y;
    const int b     = blockIdx.z;

    const float* Fb = F + (size_t)b * CHAN * HW;
    const float* Sb = S + (size_t)b * CHAN * HW;

    // ---------------- precompute load roles (compact 32-bit state) ----------------
    uint32_t s_off[S_ROLES];
    uint32_t s_smem[S_ROLES];
    uint32_t pmask = 0;
#pragma unroll
    for (int k = 0; k < S_ROLES; k++) {
        int v   = tid + k * NTHREADS;
        if (v >= S_VECS) v = 0;
        int ch  = v / (SROWS * SVEC);
        int rem = v - ch * (SROWS * SVEC);
        int row = rem / SVEC;
        int c4  = rem - row * SVEC;
        int gy  = tileY + row - MAXD;
        int gx  = tileX + c4 * 4 - MAXD;
        bool inb = (gy >= 0) && (gy < HH) && (gx >= 0) && (gx + 4 <= WW);
        pmask |= (inb ? 1u : 0u) << k;
        s_off[k]  = inb ? (uint32_t)(((size_t)ch * HW + gy * WW + gx) * 4) : 0u;
        s_smem[k] = (uint32_t)__cvta_generic_to_shared(&sS[0][ch][row][c4 * 4]);
    }
    uint32_t f_off;
    uint32_t f_smem;
    {
        int v   = (tid < F_VECS) ? tid : 0;
        int ch  = v >> 5;
        int rem = v & 31;
        int row = rem >> 3;
        int c4  = rem & 7;
        f_off  = (uint32_t)(((size_t)ch * HW + (tileY + row) * WW + tileX + c4 * 4) * 4);
        f_smem = (uint32_t)__cvta_generic_to_shared(&sF[0][ch][row][c4 * 4]);
    }

    auto issue = [&](int r) {
        uint32_t sOff = (r & 1) ? (uint32_t)S_BUF_BYTES : 0u;
        uint32_t fOff = (r & 1) ? (uint32_t)F_BUF_BYTES : 0u;
        uint32_t cOff = (uint32_t)r * (CH * HW * 4);
        const char* sB = (const char*)Sb + cOff;
        const char* fB = (const char*)Fb + cOff;
#pragma unroll
        for (int k = 0; k < S_ROLES; k++) {
            if (k < S_ROLES - 1 || tid < (S_VECS - (S_ROLES - 1) * NTHREADS)) {
                cp_async16(s_smem[k] + sOff, (const float*)(sB + s_off[k]),
                           (pmask >> k) & 1u);
            }
        }
        if (tid < F_VECS) cp_async16(f_smem + fOff, (const float*)(fB + f_off), 1u);
        asm volatile("cp.async.commit_group;\n" ::: "memory");
    };

    // accumulators:
    //  even d = 2j (j=0..4): packed f32x2, Ae[q][j] = pixels (2q, 2q+1)
    //  odd  d = 2j+1 (j=0..3): scalar, Ao[p][j] = pixel p
    u64   Ae[2][5];
    float Ao[4][4];
#pragma unroll
    for (int j = 0; j < 5; j++) { Ae[0][j] = 0ull; Ae[1][j] = 0ull; }
#pragma unroll
    for (int p = 0; p < 4; p++)
#pragma unroll
        for (int j = 0; j < 4; j++) Ao[p][j] = 0.0f;

    const int x0 = PX * tx;      // 0,4,...,28
    const int sy = ty + g;       // 0..11

    // per-channel body (identical math for any visit order)
    auto channel_body = [&](int bb, int ch) {
        // F pixels: one LDS.128
        float4 f4 = *(const float4*)&sF[bb][ch][ty][x0];
        u64 fp0 = pk(f4.x, f4.y);      // adjacent members -> 0 MOVs
        u64 fp1 = pk(f4.z, f4.w);

        // S window: 12 floats, three LDS.128
        const float4* wr4 = (const float4*)&sS[bb][ch][sy][x0];
        float4 w0 = wr4[0];
        float4 w1 = wr4[1];
        float4 w2 = wr4[2];
        float wa[12] = { w0.x, w0.y, w0.z, w0.w,
                         w1.x, w1.y, w1.z, w1.w,
                         w2.x, w2.y, w2.z, w2.w };
        // even window pairs (w[2j], w[2j+1]): adjacent members -> 0 MOVs
        u64 we[6] = { pk(w0.x, w0.y), pk(w0.z, w0.w),
                      pk(w1.x, w1.y), pk(w1.z, w1.w),
                      pk(w2.x, w2.y), pk(w2.z, w2.w) };

        // even d = 2j: pixels (0,1) need pair @ s=d; pixels (2,3) @ s=d+2
#pragma unroll
        for (int j = 0; j < 5; j++) {
            ffma2(Ae[0][j], fp0, we[j]);
            ffma2(Ae[1][j], fp1, we[j + 1]);
        }
        // odd d = 2j+1: scalar FFMA, operands straight from float4 regs
#pragma unroll
        for (int j = 0; j < 4; j++) {
            Ao[0][j] = fmaf(f4.x, wa[2 * j + 1], Ao[0][j]);
            Ao[1][j] = fmaf(f4.y, wa[2 * j + 2], Ao[1][j]);
            Ao[2][j] = fmaf(f4.z, wa[2 * j + 3], Ao[2][j]);
            Ao[3][j] = fmaf(f4.w, wa[2 * j + 4], Ao[3][j]);
        }
    };

    const bool rev = (g & 1);    // odd warps sweep channels high->low

    issue(0);

    for (int r = 0; r < NROUNDS; r++) {
        asm volatile("cp.async.wait_group 0;\n" ::: "memory");
        __syncthreads();
        if (r + 1 < NROUNDS) issue(r + 1);

        const int bb = r & 1;
        if (rev) {
#pragma unroll
            for (int ch = CH - 1; ch >= 0; ch--) channel_body(bb, ch);
        } else {
#pragma unroll
            for (int ch = 0; ch < CH; ch++) channel_body(bb, ch);
        }
    }

    // ---------------- store: scale by 1/C ----------------
    const float inv = 1.0f / (float)CHAN;
    const int y  = tileY + ty;
    const int gx = tileX + x0;
    // even disparities
#pragma unroll
    for (int j = 0; j < 5; j++) {
        int disp = g * WIN + 2 * j;
        float p0, p1, p2, p3;
        unpk(Ae[0][j], p0, p1);
        unpk(Ae[1][j], p2, p3);
        float4 v = { p0 * inv, p1 * inv, p2 * inv, p3 * inv };
        *(float4*)&out[((size_t)(b * NDISP + disp) * HH + y) * WW + gx] = v;
    }
    // odd disparities
#pragma unroll
    for (int j = 0; j < 4; j++) {
        int disp = g * WIN + 2 * j + 1;
        float4 v = { Ao[0][j] * inv, Ao[1][j] * inv,
                     Ao[2][j] * inv, Ao[3][j] * inv };
        *(float4*)&out[((size_t)(b * NDISP + disp) * HH + y) * WW + gx] = v;
    }
}

extern "C" void kernel_launch(void* const* d_in, const int* in_sizes, int n_in,
                              void* d_out, int out_size)
{
    const float* tensorFirst  = (const float*)d_in[0];
    const float* tensorSecond = (const float*)d_in[1];
    float* out = (float*)d_out;

    dim3 grid(WW / TILE_X, HH / TILE_Y, BATCH);   // 6 x 48 x 4 = 1152
    dim3 block(NTX, TILE_Y, WIN);                 // 8 x 4 x 9 = 288
    corr_kernel<<<grid, block>>>(tensorFirst, tensorSecond, out);
}

// round 16
// speedup vs baseline: 1.0716x; 1.0582x over previous
#include <cuda_runtime.h>
#include <cstdint>

// Problem constants (fixed by the reference)
#define BATCH 4
#define CHAN  256
#define HH    192
#define WW    192
#define HW    (HH*WW)
#define MAXD  4
#define WIN   9
#define NDISP 81

// Tiling
#define TILE_X 32
#define TILE_Y 4
#define PX     4                 // pixels per thread along x
#define NTX    (TILE_X / PX)     // 8
#define SROWS  (TILE_Y + 2*MAXD) // 12
#define SVEC   10                // float4s per S row (40 cols)
#define SPITCH 44                // 176B row: conflict-free, 16B aligned
#define FPITCH 36                // 144B row: conflict-free, 16B aligned
#define CH     8
#define NROUNDS (CHAN / CH)      // 32
#define NTHREADS (NTX * TILE_Y * WIN)  // 288 = 9 warps, one dy per warp

#define S_VECS (CH * SROWS * SVEC)        // 960 float4 per stage
#define F_VECS (CH * TILE_Y * (TILE_X/4)) // 256 float4 per stage
#define S_ROLES 4                          // 3 full * 288 + 96

#define S_BUF_BYTES (CH * SROWS * SPITCH * 4)   // 16896
#define F_BUF_BYTES (CH * TILE_Y * FPITCH * 4)  // 4608

typedef unsigned long long u64;

__device__ __forceinline__ void cp_async16(uint32_t saddr, const float* gptr, uint32_t full)
{
    int sz = full ? 16 : 0;   // src-size 0 -> 16B zero fill (halo)
    asm volatile("cp.async.cg.shared.global [%0], [%1], 16, %2;\n"
                 :: "r"(saddr), "l"(gptr), "r"(sz));
}

// pack two floats into b64; adjacent float4 members coalesce to 0 MOVs
__device__ __forceinline__ u64 pk(float lo, float hi)
{
    u64 v;
    asm("mov.b64 %0, {%1, %2};" : "=l"(v) : "f"(lo), "f"(hi));
    return v;
}

__device__ __forceinline__ void ffma2(u64& acc, u64 a, u64 b)
{
    asm("fma.rn.f32x2 %0, %1, %2, %3;" : "=l"(acc) : "l"(a), "l"(b), "l"(acc));
}

__device__ __forceinline__ void unpk(u64 v, float& lo, float& hi)
{
    asm("mov.b64 {%0, %1}, %2;" : "=f"(lo), "=f"(hi) : "l"(v));
}

__global__ __launch_bounds__(NTHREADS, 3)
void corr_kernel(const float* __restrict__ F,
                 const float* __restrict__ S,
                 float* __restrict__ out)
{
    __shared__ __align__(16) float sS[2][CH][SROWS][SPITCH];
    __shared__ __align__(16) float sF[2][CH][TILE_Y][FPITCH];

    const int tx = threadIdx.x;            // 0..7
    const int ty = threadIdx.y;            // 0..3
    const int g  = threadIdx.z;            // 0..8 (dy) == warp id
    const int tid = tx + NTX * ty + NTX * TILE_Y * g;

    const int tileX = blockIdx.x * TILE_X;
    const int tileY = blockIdx.y * TILE_Y;
    const int b     = blockIdx.z;

    const float* Fb = F + (size_t)b * CHAN * HW;
    const float* Sb = S + (size_t)b * CHAN * HW;

    // ---------------- precompute load roles (compact 32-bit state) ----------------
    uint32_t s_off[S_ROLES];
    uint32_t s_smem[S_ROLES];
    uint32_t pmask = 0;
#pragma unroll
    for (int k = 0; k < S_ROLES; k++) {
        int v   = tid + k * NTHREADS;
        if (v >= S_VECS) v = 0;
        int ch  = v / (SROWS * SVEC);
        int rem = v - ch * (SROWS * SVEC);
        int row = rem / SVEC;
        int c4  = rem - row * SVEC;
        int gy  = tileY + row - MAXD;
        int gx  = tileX + c4 * 4 - MAXD;
        bool inb = (gy >= 0) && (gy < HH) && (gx >= 0) && (gx + 4 <= WW);
        pmask |= (inb ? 1u : 0u) << k;
        s_off[k]  = inb ? (uint32_t)(((size_t)ch * HW + gy * WW + gx) * 4) : 0u;
        s_smem[k] = (uint32_t)__cvta_generic_to_shared(&sS[0][ch][row][c4 * 4]);
    }
    uint32_t f_off;
    uint32_t f_smem;
    {
        int v   = (tid < F_VECS) ? tid : 0;
        int ch  = v >> 5;
        int rem = v & 31;
        int row = rem >> 3;
        int c4  = rem & 7;
        f_off  = (uint32_t)(((size_t)ch * HW + (tileY + row) * WW + tileX + c4 * 4) * 4);
        f_smem = (uint32_t)__cvta_generic_to_shared(&sF[0][ch][row][c4 * 4]);
    }

    auto issue = [&](int r) {
        uint32_t sOff = (r & 1) ? (uint32_t)S_BUF_BYTES : 0u;
        uint32_t fOff = (r & 1) ? (uint32_t)F_BUF_BYTES : 0u;
        uint32_t cOff = (uint32_t)r * (CH * HW * 4);
        const char* sB = (const char*)Sb + cOff;
        const char* fB = (const char*)Fb + cOff;
#pragma unroll
        for (int k = 0; k < S_ROLES; k++) {
            if (k < S_ROLES - 1 || tid < (S_VECS - (S_ROLES - 1) * NTHREADS)) {
                cp_async16(s_smem[k] + sOff, (const float*)(sB + s_off[k]),
                           (pmask >> k) & 1u);
            }
        }
        if (tid < F_VECS) cp_async16(f_smem + fOff, (const float*)(fB + f_off), 1u);
        asm volatile("cp.async.commit_group;\n" ::: "memory");
    };

    // accumulators:
    //  even d = 2j (j=0..4): packed f32x2, Ae[q][j] = pixels (2q, 2q+1)
    //  odd  d = 2j+1 (j=0..3): scalar, Ao[p][j] = pixel p
    u64   Ae[2][5];
    float Ao[4][4];
#pragma unroll
    for (int j = 0; j < 5; j++) { Ae[0][j] = 0ull; Ae[1][j] = 0ull; }
#pragma unroll
    for (int p = 0; p < 4; p++)
#pragma unroll
        for (int j = 0; j < 4; j++) Ao[p][j] = 0.0f;

    const int x0 = PX * tx;      // 0,4,...,28
    const int sy = ty + g;       // 0..11

    issue(0);

    for (int r = 0; r < NROUNDS; r++) {
        asm volatile("cp.async.wait_group 0;\n" ::: "memory");
        __syncthreads();
        if (r + 1 < NROUNDS) issue(r + 1);

        const int bb = r & 1;
#pragma unroll
        for (int ch = 0; ch < CH; ch++) {
            // F pixels: one LDS.128
            float4 f4 = *(const float4*)&sF[bb][ch][ty][x0];
            u64 fp0 = pk(f4.x, f4.y);      // adjacent members -> 0 MOVs
            u64 fp1 = pk(f4.z, f4.w);

            // S window: 12 floats, three LDS.128
            const float4* wr4 = (const float4*)&sS[bb][ch][sy][x0];
            float4 w0 = wr4[0];
            float4 w1 = wr4[1];
            float4 w2 = wr4[2];
            float wa[12] = { w0.x, w0.y, w0.z, w0.w,
                             w1.x, w1.y, w1.z, w1.w,
                             w2.x, w2.y, w2.z, w2.w };
            // even window pairs (w[2j], w[2j+1]): adjacent members -> 0 MOVs
            u64 we[6] = { pk(w0.x, w0.y), pk(w0.z, w0.w),
                          pk(w1.x, w1.y), pk(w1.z, w1.w),
                          pk(w2.x, w2.y), pk(w2.z, w2.w) };

            // even d = 2j: pixels (0,1) need pair @ s=d; pixels (2,3) @ s=d+2
#pragma unroll
            for (int j = 0; j < 5; j++) {
                ffma2(Ae[0][j], fp0, we[j]);
                ffma2(Ae[1][j], fp1, we[j + 1]);
            }
            // odd d = 2j+1: scalar FFMA, operands straight from float4 regs
#pragma unroll
            for (int j = 0; j < 4; j++) {
                Ao[0][j] = fmaf(f4.x, wa[2 * j + 1], Ao[0][j]);
                Ao[1][j] = fmaf(f4.y, wa[2 * j + 2], Ao[1][j]);
                Ao[2][j] = fmaf(f4.z, wa[2 * j + 3], Ao[2][j]);
                Ao[3][j] = fmaf(f4.w, wa[2 * j + 4], Ao[3][j]);
            }
        }
    }

    // ---------------- store: scale by 1/C ----------------
    const float inv = 1.0f / (float)CHAN;
    const int y  = tileY + ty;
    const int gx = tileX + x0;
    // even disparities
#pragma unroll
    for (int j = 0; j < 5; j++) {
        int disp = g * WIN + 2 * j;
        float p0, p1, p2, p3;
        unpk(Ae[0][j], p0, p1);
        unpk(Ae[1][j], p2, p3);
        float4 v = { p0 * inv, p1 * inv, p2 * inv, p3 * inv };
        *(float4*)&out[((size_t)(b * NDISP + disp) * HH + y) * WW + gx] = v;
    }
    // odd disparities
#pragma unroll
    for (int j = 0; j < 4; j++) {
        int disp = g * WIN + 2 * j + 1;
        float4 v = { Ao[0][j] * inv, Ao[1][j] * inv,
                     Ao[2][j] * inv, Ao[3][j] * inv };
        *(float4*)&out[((size_t)(b * NDISP + disp) * HH + y) * WW + gx] = v;
    }
}

extern "C" void kernel_launch(void* const* d_in, const int* in_sizes, int n_in,
                              void* d_out, int out_size)
{
    const float* tensorFirst  = (const float*)d_in[0];
    const float* tensorSecond = (const float*)d_in[1];
    float* out = (float*)d_out;

    dim3 grid(WW / TILE_X, HH / TILE_Y, BATCH);   // 6 x 48 x 4 = 1152
    dim3 block(NTX, TILE_Y, WIN);                 // 8 x 4 x 9 = 288
    corr_kernel<<<grid, block>>>(tensorFirst, tensorSecond, out);
}